// round 15
// baseline (speedup 1.0000x reference)
#include <cuda_runtime.h>
#include <cuda_fp16.h>
#include <math.h>

#define Bv 4
#define Mv 1024
#define Hv 1024
#define NHv 8
#define Dv 128
#define Lv 1024
#define Ev 8
#define Fv 4096
#define NTOK (Bv*Mv)      /* 4096 */
#define LMv (Lv+Mv)       /* 2048 */
#define BHv (Bv*NHv)      /* 32 */
#define SKW 1152          /* skewed row width = 1024 + 128 */
#define NSPL 3            /* flash KV splits */

// ---------------- scratch (device globals; no allocation allowed) ----------------
__device__ float  g_sskew[(size_t)BHv*Mv*SKW];   // skewed pos scores (fp32)
__device__ float  g_proj[(size_t)NTOK*Hv];
__device__ float  g_h1[(size_t)NTOK*Hv];
__device__ float  g_y[(size_t)Ev*NTOK*Hv];       // per-slot weighted expert outputs
__device__ int    g_cnt[Ev];
__device__ int    g_elist[Ev*NTOK];
__device__ float  g_ew[Ev*NTOK];
__device__ int    g_tslot[NTOK*2];               // token -> 2 global slot rows
__device__ float  g_opart[(size_t)NSPL*BHv*Mv*Dv];  // split-KV partial O
__device__ float  g_ml[(size_t)NSPL*BHv*Mv*2];      // split-KV partial (m, l)
// fp16 operands
__device__ __half g_hall16[(size_t)Bv*LMv*Hv];
__device__ __half g_h16[(size_t)NTOK*Hv];
__device__ __half g_q16[(size_t)NTOK*Hv];
__device__ __half g_k16[(size_t)Bv*LMv*Hv];
__device__ __half g_v16[(size_t)Bv*LMv*Hv];
__device__ __half g_pos16[(size_t)Dv*Lv];
__device__ __half g_wq16[(size_t)Hv*Hv];
__device__ __half g_wk16[(size_t)Hv*Hv];
__device__ __half g_wv16[(size_t)Hv*Hv];
__device__ __half g_wo16[(size_t)Hv*Hv];
__device__ __half g_w1h[(size_t)Ev*Hv*Fv];
__device__ __half g_w2h[(size_t)Ev*Fv*Hv];
__device__ __half g_attn16[(size_t)NTOK*Hv];
__device__ __half g_h1h[(size_t)NTOK*Hv];
__device__ __half g_act16[(size_t)Ev*NTOK*Fv];   // per-expert packed activations

__device__ __forceinline__ unsigned sptr(const void* p){
    unsigned r;
    asm("{.reg .u64 t; cvta.to.shared.u64 t, %1; cvt.u32.u64 %0, t;}" : "=r"(r) : "l"(p));
    return r;
}

// ---------------- fp32 -> fp16 conversion (8 elems/thread) ----------------
__global__ void cvt_kernel(const float* __restrict__ src, __half* __restrict__ dst, size_t n)
{
    size_t i = ((size_t)blockIdx.x*256 + threadIdx.x)*8;
    if (i >= n) return;
    float4 a = *(const float4*)(src+i);
    float4 b = *(const float4*)(src+i+4);
    __half2 h0 = __floats2half2_rn(a.x,a.y);
    __half2 h1 = __floats2half2_rn(a.z,a.w);
    __half2 h2 = __floats2half2_rn(b.x,b.y);
    __half2 h3 = __floats2half2_rn(b.z,b.w);
    uint4 o;
    o.x = *(unsigned*)&h0; o.y = *(unsigned*)&h1;
    o.z = *(unsigned*)&h2; o.w = *(unsigned*)&h3;
    *(uint4*)(dst+i) = o;
}

// ---------------- concat h_all = [h_cache ; h] -> fp16 ----------------
__global__ void concat_kernel(const float* __restrict__ h_cache, const float* __restrict__ h)
{
    size_t i4 = (size_t)blockIdx.x * blockDim.x + threadIdx.x;
    size_t total4 = (size_t)Bv*LMv*Hv/4;
    if (i4 >= total4) return;
    size_t gi = i4*4;
    int b = (int)(gi / ((size_t)LMv*Hv));
    size_t off = gi - (size_t)b*LMv*Hv;
    float4 val;
    if (off < (size_t)Lv*Hv)
        val = *(const float4*)(h_cache + (size_t)b*Lv*Hv + off);
    else
        val = *(const float4*)(h + (size_t)b*Mv*Hv + (off - (size_t)Lv*Hv));
    __half2 h0 = __floats2half2_rn(val.x,val.y);
    __half2 h1 = __floats2half2_rn(val.z,val.w);
    uint2 o; o.x = *(unsigned*)&h0; o.y = *(unsigned*)&h1;
    *(uint2*)(g_hall16 + gi) = o;
}

// ---------------- fp16 tensor-core GEMM, 128x128x32 tile, 4-stage cp.async ----------
// MODE 0: C(f32) = acc
// MODE 1: z=expert: A rows gathered via elist; C16=act16+e pack = relu(acc+bias)
// MODE 2: z=expert: A=act16+e pack; C(f32)=y pack: y[e*NTOK+rm] = w*(acc+bias)
// MODE 3: z=bh: pos GEMM, A=q16 slice (lda=Hv); C=sskew skewed store *1/32
// MODE 4: C16 = acc
#define ASTR 40
#define BSTR 136
#define NSTG 4
#define STAGEA (128*ASTR)
#define STAGEB (32*BSTR)
#define SMEMSZ ((STAGEA+STAGEB)*NSTG*2)
template<int MODE>
__global__ void __launch_bounds__(256,2) hgemm(
    const __half* __restrict__ A, const __half* __restrict__ B,
    float* __restrict__ C, __half* __restrict__ C16,
    int M, int N, int K, int lda,
    const int* __restrict__ rowidx, const int* __restrict__ Mptr,
    const float* __restrict__ bias,
    const float* __restrict__ wrow)
{
    extern __shared__ __half dsm[];
    __half* As = dsm;
    __half* Bs = dsm + (size_t)NSTG*STAGEA;

    int m0 = blockIdx.y * 128;
    int n0 = blockIdx.x * 128;
    int Klim = 1 << 30;
    const __half* Ap = A; const __half* Bp = B;
    float* Cp = C; __half* C16p = C16;
    const int* rix = rowidx;
    const float* wro = wrow;
    if (MODE == 1) {
        int e = blockIdx.z;
        rix   = rowidx + e*NTOK;
        Mptr += e;
        Bp   += (size_t)e*K*N;
        bias += (size_t)e*N;
        C16p += (size_t)e*NTOK*N;
    }
    if (MODE == 2) {
        int e = blockIdx.z;
        Ap   += (size_t)e*NTOK*K;
        Mptr += e;
        Bp   += (size_t)e*K*N;
        bias += (size_t)e*N;
        wro   = wrow + e*NTOK;
        Cp   += (size_t)e*NTOK*N;
    }
    if (MODE == 3) {
        int z = blockIdx.z;
        Ap  += ((size_t)(z>>3)*Mv)*Hv + (size_t)(z&7)*Dv;
        Cp  += (size_t)z*Mv*SKW;
    }
    int Meff = Mptr ? *Mptr : M;
    if (m0 >= Meff) return;

    int tid = threadIdx.x;
    int wid = tid >> 5, lane = tid & 31;
    int wr = wid >> 2, wc = wid & 3;
    int g = lane >> 2, tig = lane & 3;

    int arow0 = tid >> 2,           ach0 = tid & 3;
    int arow1 = (tid+256) >> 2,     ach1 = (tid+256) & 3;
    int gr0 = m0 + arow0, gr1 = m0 + arow1;
    bool v0 = gr0 < Meff, v1 = gr1 < Meff;
    int grr0 = gr0, grr1 = gr1;
    if (MODE == 1) { grr0 = v0 ? rix[gr0] : 0; grr1 = v1 ? rix[gr1] : 0; }
    const __half* asrc0 = Ap + (size_t)grr0*lda + ach0*8;
    const __half* asrc1 = Ap + (size_t)grr1*lda + ach1*8;
    unsigned aS = sptr(As), bS = sptr(Bs);
    unsigned adst0 = aS + (unsigned)((arow0*ASTR + ach0*8)*2);
    unsigned adst1 = aS + (unsigned)((arow1*ASTR + ach1*8)*2);
    int asz0 = v0 ? 16 : 0, asz1 = v1 ? 16 : 0;
    int bk0 = tid >> 4,         bc0 = tid & 15;
    int bk1 = (tid+256) >> 4,   bc1 = (tid+256) & 15;
    const __half* bsrc0 = Bp + (size_t)bk0*N + n0 + bc0*8;
    const __half* bsrc1 = Bp + (size_t)bk1*N + n0 + bc1*8;
    unsigned bdst0 = bS + (unsigned)((bk0*BSTR + bc0*8)*2);
    unsigned bdst1 = bS + (unsigned)((bk1*BSTR + bc1*8)*2);

    float acc[4][4][4];
    #pragma unroll
    for (int a=0;a<4;a++)
        #pragma unroll
        for (int b=0;b<4;b++)
            #pragma unroll
            for (int c=0;c<4;c++) acc[a][b][c]=0.f;

    #define ISSUE(s, kt) do { \
        size_t ka = (size_t)(kt)*32; \
        size_t kb = (size_t)(kt)*32*N; \
        int bs0 = ((kt)*32 + bk0 < Klim) ? 16 : 0; \
        int bs1 = ((kt)*32 + bk1 < Klim) ? 16 : 0; \
        unsigned oa = (unsigned)((s)*STAGEA*2), ob = (unsigned)((s)*STAGEB*2); \
        asm volatile("cp.async.cg.shared.global [%0], [%1], 16, %2;" :: "r"(adst0+oa), "l"(asrc0 + ka), "r"(asz0)); \
        asm volatile("cp.async.cg.shared.global [%0], [%1], 16, %2;" :: "r"(adst1+oa), "l"(asrc1 + ka), "r"(asz1)); \
        asm volatile("cp.async.cg.shared.global [%0], [%1], 16, %2;" :: "r"(bdst0+ob), "l"(bsrc0 + kb), "r"(bs0)); \
        asm volatile("cp.async.cg.shared.global [%0], [%1], 16, %2;" :: "r"(bdst1+ob), "l"(bsrc1 + kb), "r"(bs1)); \
        asm volatile("cp.async.commit_group;"); \
    } while(0)

    int nK = K >> 5;
    #pragma unroll
    for (int t = 0; t < NSTG-1; t++) {
        if (t < nK) ISSUE(t, t);
        else asm volatile("cp.async.commit_group;");
    }
    int arow = wr*64 + (lane & 15);
    int acolbase = (lane >> 4) * 8;
    int brow = lane & 15;

    for (int kt = 0; kt < nK; kt++) {
        int tnext = kt + NSTG - 1;
        if (tnext < nK) ISSUE(tnext & (NSTG-1), tnext);
        else asm volatile("cp.async.commit_group;");
        asm volatile("cp.async.wait_group %0;" :: "n"(NSTG-1));
        __syncthreads();
        int s = kt & (NSTG-1);
        unsigned abase = aS + (unsigned)(s*STAGEA*2);
        unsigned bbase = bS + (unsigned)(s*STAGEB*2);
        #pragma unroll
        for (int ks = 0; ks < 2; ks++) {
            unsigned a[4][4], bfr[2][4];
            int acol = ks*16 + acolbase;
            #pragma unroll
            for (int mt=0;mt<4;mt++){
                unsigned ad = abase + (unsigned)(((arow + mt*16)*ASTR + acol)*2);
                asm volatile("ldmatrix.sync.aligned.m8n8.x4.shared.b16 {%0,%1,%2,%3}, [%4];"
                    : "=r"(a[mt][0]), "=r"(a[mt][1]), "=r"(a[mt][2]), "=r"(a[mt][3]) : "r"(ad));
            }
            #pragma unroll
            for (int pr=0;pr<2;pr++){
                int bcol = wc*32 + pr*16 + acolbase;
                unsigned bd = bbase + (unsigned)(((ks*16 + brow)*BSTR + bcol)*2);
                asm volatile("ldmatrix.sync.aligned.m8n8.x4.trans.shared.b16 {%0,%1,%2,%3}, [%4];"
                    : "=r"(bfr[pr][0]), "=r"(bfr[pr][1]), "=r"(bfr[pr][2]), "=r"(bfr[pr][3]) : "r"(bd));
            }
            #pragma unroll
            for (int mt=0;mt<4;mt++)
                #pragma unroll
                for (int nt=0;nt<4;nt++){
                    unsigned b0 = bfr[nt>>1][(nt&1)*2+0];
                    unsigned b1 = bfr[nt>>1][(nt&1)*2+1];
                    asm volatile(
                        "mma.sync.aligned.m16n8k16.row.col.f32.f16.f16.f32 "
                        "{%0,%1,%2,%3}, {%4,%5,%6,%7}, {%8,%9}, {%0,%1,%2,%3};"
                        : "+f"(acc[mt][nt][0]), "+f"(acc[mt][nt][1]),
                          "+f"(acc[mt][nt][2]), "+f"(acc[mt][nt][3])
                        : "r"(a[mt][0]), "r"(a[mt][1]), "r"(a[mt][2]), "r"(a[mt][3]),
                          "r"(b0), "r"(b1));
                }
        }
        __syncthreads();
    }

    // epilogue
    #pragma unroll
    for (int mt=0;mt<4;mt++){
        #pragma unroll
        for (int half=0; half<2; half++){
            int rm = m0 + wr*64 + mt*16 + g + half*8;
            if (rm >= Meff) continue;
            #pragma unroll
            for (int nt=0;nt<4;nt++){
                int cn = n0 + wc*32 + nt*8 + tig*2;
                float c0 = acc[mt][nt][half*2+0];
                float c1 = acc[mt][nt][half*2+1];
                if (MODE == 0) {
                    float* cp = Cp + (size_t)rm*N + cn;
                    cp[0] = c0; cp[1] = c1;
                } else if (MODE == 1) {
                    __half* cp = C16p + (size_t)rm*N + cn;
                    cp[0] = __float2half_rn(fmaxf(c0 + bias[cn],   0.f));
                    cp[1] = __float2half_rn(fmaxf(c1 + bias[cn+1], 0.f));
                } else if (MODE == 2) {
                    float w = wro[rm];
                    float* cp = Cp + (size_t)rm*N + cn;
                    cp[0] = w * (c0 + bias[cn]);
                    cp[1] = w * (c1 + bias[cn+1]);
                } else if (MODE == 3) {
                    float* cp = Cp + (size_t)rm*SKW + cn + (rm & 127);
                    cp[0] = c0 * 0.03125f;
                    cp[1] = c1 * 0.03125f;
                } else { // MODE 4
                    __half* cp = C16p + (size_t)rm*N + cn;
                    cp[0] = __float2half_rn(c0);
                    cp[1] = __float2half_rn(c1);
                }
            }
        }
    }
}

// ---------------- split-KV fused flash attention ----------------
// grid (8 mtiles, 32 bh, NSPL splits); each split handles 6 of 18 chunks,
// emits unnormalized O_partial (fp32) + per-row (m, l).
#define FSTR 136
#define FSMEM ((128*FSTR + 2*64*FSTR + 2*64*FSTR)*2)
__global__ void __launch_bounds__(256,1) flash_kernel(
    const __half* __restrict__ q16, const __half* __restrict__ k16,
    const __half* __restrict__ v16, const float* __restrict__ sskew,
    float* __restrict__ opart, float* __restrict__ ml)
{
    extern __shared__ __half fsm[];
    __half* Qs = fsm;
    __half* Ks = fsm + 128*FSTR;
    __half* Vs = Ks + 2*64*FSTR;
    int m0 = blockIdx.x * 128;
    int bh = blockIdx.y;
    int spl = blockIdx.z;
    int cbeg = spl * 6;
    int b = bh >> 3, nh = bh & 7;
    int tid = threadIdx.x, wid = tid >> 5, lane = tid & 31;
    int g = lane >> 2, tig = lane & 3;
    int R0 = wid * 16;

    {
        int row = tid >> 1, seg = tid & 1;
        const uint4* src = (const uint4*)(q16 + ((size_t)(b*Mv + m0 + row))*Hv + nh*Dv + seg*64);
        uint4* dst = (uint4*)(Qs + row*FSTR + seg*64);
        #pragma unroll
        for (int i=0;i<8;i++) dst[i] = src[i];
    }
    const __half* ksrc[4]; const __half* vsrc[4]; unsigned kvoff[4];
    #pragma unroll
    for (int i=0;i<4;i++){
        int lin = tid + i*256;
        int row = lin >> 4, ch = lin & 15;
        ksrc[i] = k16 + ((size_t)(b*LMv + m0 + row))*Hv + nh*Dv + ch*8;
        vsrc[i] = v16 + ((size_t)(b*LMv + m0 + row))*Hv + nh*Dv + ch*8;
        kvoff[i] = (unsigned)((row*FSTR + ch*8)*2);
    }
    unsigned kS = sptr(Ks), vS = sptr(Vs);

    #define FLD(s, c) do { \
        size_t go = (size_t)(c)*64*Hv; \
        unsigned so = (unsigned)((s)*64*FSTR*2); \
        _Pragma("unroll") \
        for (int i=0;i<4;i++) \
            asm volatile("cp.async.cg.shared.global [%0], [%1], 16;" :: "r"(kS + so + kvoff[i]), "l"(ksrc[i] + go)); \
        _Pragma("unroll") \
        for (int i=0;i<4;i++) \
            asm volatile("cp.async.cg.shared.global [%0], [%1], 16;" :: "r"(vS + so + kvoff[i]), "l"(vsrc[i] + go)); \
        asm volatile("cp.async.commit_group;"); \
    } while(0)

    FLD(0, cbeg);
    __syncthreads();

    unsigned qf[8][4];
    {
        unsigned qbase = sptr(Qs);
        int arow = R0 + (lane & 15);
        int acolsel = (lane >> 4) * 8;
        #pragma unroll
        for (int ks=0; ks<8; ks++){
            unsigned ad = qbase + (unsigned)((arow*FSTR + ks*16 + acolsel)*2);
            asm volatile("ldmatrix.sync.aligned.m8n8.x4.shared.b16 {%0,%1,%2,%3}, [%4];"
                : "=r"(qf[ks][0]), "=r"(qf[ks][1]), "=r"(qf[ks][2]), "=r"(qf[ks][3]) : "r"(ad));
        }
    }

    float of[16][4];
    #pragma unroll
    for (int i=0;i<16;i++)
        #pragma unroll
        for (int q=0;q<4;q++) of[i][q]=0.f;
    float mrun0 = -1e30f, mrun1 = -1e30f;
    float lrun0 = 0.f, lrun1 = 0.f;

    int r0l = R0 + g, r1l = R0 + g + 8;
    const float* posr0 = sskew + ((size_t)(bh*Mv + m0 + r0l))*SKW;
    const float* posr1 = sskew + ((size_t)(bh*Mv + m0 + r1l))*SKW;
    int kb_row = (lane & 7) + ((lane >> 4) << 3);
    int kb_csel = ((lane >> 3) & 1) * 8;

    for (int c = cbeg; c < cbeg + 6; c++) {
        int s = (c - cbeg) & 1;
        if (c + 1 < cbeg + 6) { FLD(1-s, c+1); asm volatile("cp.async.wait_group 1;"); }
        else                    asm volatile("cp.async.wait_group 0;");
        __syncthreads();
        unsigned kbase = kS + (unsigned)(s*64*FSTR*2);
        unsigned vbase = vS + (unsigned)(s*64*FSTR*2);

        float sacc[8][4];
        #pragma unroll
        for (int nt=0;nt<8;nt++)
            #pragma unroll
            for (int q=0;q<4;q++) sacc[nt][q]=0.f;
        #pragma unroll
        for (int ks=0; ks<8; ks++){
            #pragma unroll
            for (int np=0; np<4; np++){
                unsigned bb0,bb1,bb2,bb3;
                unsigned bd = kbase + (unsigned)(((np*16 + kb_row)*FSTR + ks*16 + kb_csel)*2);
                asm volatile("ldmatrix.sync.aligned.m8n8.x4.shared.b16 {%0,%1,%2,%3}, [%4];"
                    : "=r"(bb0), "=r"(bb1), "=r"(bb2), "=r"(bb3) : "r"(bd));
                asm volatile(
                    "mma.sync.aligned.m16n8k16.row.col.f32.f16.f16.f32 "
                    "{%0,%1,%2,%3}, {%4,%5,%6,%7}, {%8,%9}, {%0,%1,%2,%3};"
                    : "+f"(sacc[np*2][0]), "+f"(sacc[np*2][1]), "+f"(sacc[np*2][2]), "+f"(sacc[np*2][3])
                    : "r"(qf[ks][0]), "r"(qf[ks][1]), "r"(qf[ks][2]), "r"(qf[ks][3]),
                      "r"(bb0), "r"(bb1));
                asm volatile(
                    "mma.sync.aligned.m16n8k16.row.col.f32.f16.f16.f32 "
                    "{%0,%1,%2,%3}, {%4,%5,%6,%7}, {%8,%9}, {%0,%1,%2,%3};"
                    : "+f"(sacc[np*2+1][0]), "+f"(sacc[np*2+1][1]), "+f"(sacc[np*2+1][2]), "+f"(sacc[np*2+1][3])
                    : "r"(qf[ks][0]), "r"(qf[ks][1]), "r"(qf[ks][2]), "r"(qf[ks][3]),
                      "r"(bb2), "r"(bb3));
            }
        }

        float cm0 = -1e30f, cm1 = -1e30f;
        #pragma unroll
        for (int nt=0;nt<8;nt++){
            int o0 = nt*8 + tig*2;
            int u0 = c*64 + o0, u1 = u0 + 1;
            int ja = u0 - r0l, jb = u1 - r0l;
            float s0 = ((unsigned)ja < 1024u) ? sacc[nt][0]*0.03125f + posr0[u0] : -1e30f;
            float s1 = ((unsigned)jb < 1024u) ? sacc[nt][1]*0.03125f + posr0[u1] : -1e30f;
            int jc = u0 - r1l, jd = u1 - r1l;
            float s2 = ((unsigned)jc < 1024u) ? sacc[nt][2]*0.03125f + posr1[u0] : -1e30f;
            float s3 = ((unsigned)jd < 1024u) ? sacc[nt][3]*0.03125f + posr1[u1] : -1e30f;
            sacc[nt][0]=s0; sacc[nt][1]=s1; sacc[nt][2]=s2; sacc[nt][3]=s3;
            cm0 = fmaxf(cm0, fmaxf(s0, s1));
            cm1 = fmaxf(cm1, fmaxf(s2, s3));
        }
        cm0 = fmaxf(cm0, __shfl_xor_sync(0xffffffffu, cm0, 1));
        cm0 = fmaxf(cm0, __shfl_xor_sync(0xffffffffu, cm0, 2));
        cm1 = fmaxf(cm1, __shfl_xor_sync(0xffffffffu, cm1, 1));
        cm1 = fmaxf(cm1, __shfl_xor_sync(0xffffffffu, cm1, 2));
        float mn0 = fmaxf(mrun0, cm0), mn1 = fmaxf(mrun1, cm1);
        float sc0 = (mrun0 == mn0) ? 1.f : __expf(mrun0 - mn0);
        float sc1 = (mrun1 == mn1) ? 1.f : __expf(mrun1 - mn1);
        float me0 = (mn0 == -1e30f) ? 0.f : mn0;
        float me1 = (mn1 == -1e30f) ? 0.f : mn1;
        float ls0 = 0.f, ls1 = 0.f;
        #pragma unroll
        for (int nt=0;nt<8;nt++){
            float p0 = __expf(sacc[nt][0] - me0);
            float p1 = __expf(sacc[nt][1] - me0);
            float p2 = __expf(sacc[nt][2] - me1);
            float p3 = __expf(sacc[nt][3] - me1);
            sacc[nt][0]=p0; sacc[nt][1]=p1; sacc[nt][2]=p2; sacc[nt][3]=p3;
            ls0 += p0 + p1; ls1 += p2 + p3;
        }
        lrun0 = lrun0*sc0 + ls0;
        lrun1 = lrun1*sc1 + ls1;
        mrun0 = mn0; mrun1 = mn1;
        #pragma unroll
        for (int i=0;i<16;i++){
            of[i][0]*=sc0; of[i][1]*=sc0; of[i][2]*=sc1; of[i][3]*=sc1;
        }

        #pragma unroll
        for (int kc=0; kc<4; kc++){
            __half2 h0 = __floats2half2_rn(sacc[2*kc][0],   sacc[2*kc][1]);
            __half2 h1 = __floats2half2_rn(sacc[2*kc][2],   sacc[2*kc][3]);
            __half2 h2 = __floats2half2_rn(sacc[2*kc+1][0], sacc[2*kc+1][1]);
            __half2 h3 = __floats2half2_rn(sacc[2*kc+1][2], sacc[2*kc+1][3]);
            unsigned pa0 = *(unsigned*)&h0, pa1 = *(unsigned*)&h1;
            unsigned pa2 = *(unsigned*)&h2, pa3 = *(unsigned*)&h3;
            #pragma unroll
            for (int np=0; np<8; np++){
                unsigned vb0,vb1,vb2,vb3;
                unsigned bd = vbase + (unsigned)(((kc*16 + (lane & 15))*FSTR + np*16 + (lane>>4)*8)*2);
                asm volatile("ldmatrix.sync.aligned.m8n8.x4.trans.shared.b16 {%0,%1,%2,%3}, [%4];"
                    : "=r"(vb0), "=r"(vb1), "=r"(vb2), "=r"(vb3) : "r"(bd));
                asm volatile(
                    "mma.sync.aligned.m16n8k16.row.col.f32.f16.f16.f32 "
                    "{%0,%1,%2,%3}, {%4,%5,%6,%7}, {%8,%9}, {%0,%1,%2,%3};"
                    : "+f"(of[np*2][0]), "+f"(of[np*2][1]), "+f"(of[np*2][2]), "+f"(of[np*2][3])
                    : "r"(pa0), "r"(pa1), "r"(pa2), "r"(pa3), "r"(vb0), "r"(vb1));
                asm volatile(
                    "mma.sync.aligned.m16n8k16.row.col.f32.f16.f16.f32 "
                    "{%0,%1,%2,%3}, {%4,%5,%6,%7}, {%8,%9}, {%0,%1,%2,%3};"
                    : "+f"(of[np*2+1][0]), "+f"(of[np*2+1][1]), "+f"(of[np*2+1][2]), "+f"(of[np*2+1][3])
                    : "r"(pa0), "r"(pa1), "r"(pa2), "r"(pa3), "r"(vb2), "r"(vb3));
            }
        }
        __syncthreads();
    }

    // reduce l within quad; write unnormalized partials + (m, l)
    lrun0 += __shfl_xor_sync(0xffffffffu, lrun0, 1);
    lrun0 += __shfl_xor_sync(0xffffffffu, lrun0, 2);
    lrun1 += __shfl_xor_sync(0xffffffffu, lrun1, 1);
    lrun1 += __shfl_xor_sync(0xffffffffu, lrun1, 2);
    size_t base = ((size_t)spl*BHv + bh)*Mv + m0;
    float* o0p = opart + (base + r0l)*Dv;
    float* o1p = opart + (base + r1l)*Dv;
    #pragma unroll
    for (int nt=0; nt<16; nt++){
        int colb = nt*8 + tig*2;
        o0p[colb]   = of[nt][0]; o0p[colb+1] = of[nt][1];
        o1p[colb]   = of[nt][2]; o1p[colb+1] = of[nt][3];
    }
    if (tig == 0) {
        ml[(base + r0l)*2]   = mrun0;
        ml[(base + r0l)*2+1] = lrun0;
        ml[(base + r1l)*2]   = mrun1;
        ml[(base + r1l)*2+1] = lrun1;
    }
}

// ---------------- combine split-KV partials -> attn16 ----------------
// grid BHv*Mv blocks, 128 threads (one per d column)
__global__ void combine_kernel(const float* __restrict__ opart, const float* __restrict__ ml,
                               __half* __restrict__ attn16)
{
    size_t row = blockIdx.x;          // bh*Mv + m
    int bh = (int)(row >> 10);
    int b = bh >> 3, nh = bh & 7;
    int m = (int)(row & 1023);
    int tid = threadIdx.x;
    float mi[NSPL], li[NSPL];
    float M = -1e30f;
    #pragma unroll
    for (int s=0; s<NSPL; s++){
        mi[s] = ml[((size_t)s*BHv*Mv + row)*2];
        li[s] = ml[((size_t)s*BHv*Mv + row)*2+1];
        M = fmaxf(M, mi[s]);
    }
    float L = 0.f, w[NSPL];
    #pragma unroll
    for (int s=0; s<NSPL; s++){
        w[s] = (li[s] > 0.f) ? __expf(mi[s] - M) : 0.f;
        L += li[s] * w[s];
    }
    float o = 0.f;
    #pragma unroll
    for (int s=0; s<NSPL; s++)
        o += w[s] * opart[((size_t)s*BHv*Mv + row)*Dv + tid];
    attn16[((size_t)(b*Mv + m))*Hv + nh*Dv + tid] = __float2half_rn(o / L);
}

// ---------------- h1 = LN(h + proj); writes fp32 + fp16 ----------------
__global__ void ln1_kernel(const float* __restrict__ h, const float* __restrict__ g,
                           const float* __restrict__ bet)
{
    int row = blockIdx.x;
    int tid = threadIdx.x;
    float4 x = ((const float4*)(h + (size_t)row*Hv))[tid];
    float4 y = ((const float4*)(g_proj + (size_t)row*Hv))[tid];
    x.x+=y.x; x.y+=y.y; x.z+=y.z; x.w+=y.w;
    __shared__ float rs[256], rq[256];
    rs[tid] = x.x+x.y+x.z+x.w;
    rq[tid] = x.x*x.x + x.y*x.y + x.z*x.z + x.w*x.w;
    __syncthreads();
    for (int t=128;t>0;t>>=1){ if(tid<t){rs[tid]+=rs[tid+t]; rq[tid]+=rq[tid+t];} __syncthreads(); }
    float mean = rs[0] * (1.f/(float)Hv);
    float var  = rq[0] * (1.f/(float)Hv) - mean*mean;
    float inv = rsqrtf(var + 1e-5f);
    float4 gg = ((const float4*)g)[tid];
    float4 bb = ((const float4*)bet)[tid];
    float4 o;
    o.x = (x.x-mean)*inv*gg.x + bb.x;
    o.y = (x.y-mean)*inv*gg.y + bb.y;
    o.z = (x.z-mean)*inv*gg.z + bb.z;
    o.w = (x.w-mean)*inv*gg.w + bb.w;
    ((float4*)(g_h1 + (size_t)row*Hv))[tid] = o;
    __half2 h0 = __floats2half2_rn(o.x,o.y);
    __half2 h1 = __floats2half2_rn(o.z,o.w);
    uint2 u; u.x = *(unsigned*)&h0; u.y = *(unsigned*)&h1;
    ((uint2*)(g_h1h + (size_t)row*Hv))[tid] = u;
}

// ---------------- gating: top-2 routing ----------------
__global__ void gate_kernel(const float* __restrict__ gw, const float* __restrict__ gb)
{
    int t = blockIdx.x;
    int tid = threadIdx.x;
    float acc[8];
    #pragma unroll
    for (int e=0;e<8;e++) acc[e]=0.f;
    for (int hh = tid; hh < Hv; hh += 256) {
        float x = g_h1[(size_t)t*Hv + hh];
        const float* gr = gw + (size_t)hh*8;
        #pragma unroll
        for (int e=0;e<8;e++) acc[e] = fmaf(x, gr[e], acc[e]);
    }
    #pragma unroll
    for (int e=0;e<8;e++)
        #pragma unroll
        for (int o=16;o>0;o>>=1) acc[e] += __shfl_xor_sync(0xffffffffu, acc[e], o);
    __shared__ float s[8][8];
    int w = tid >> 5, ln = tid & 31;
    if (ln == 0) {
        #pragma unroll
        for (int e=0;e<8;e++) s[w][e] = acc[e];
    }
    __syncthreads();
    if (tid == 0) {
        float lg[8];
        #pragma unroll
        for (int e=0;e<8;e++){
            float v = gb[e];
            #pragma unroll
            for (int w2=0;w2<8;w2++) v += s[w2][e];
            lg[e] = v;
        }
        int i0 = 0;
        #pragma unroll
        for (int e=1;e<8;e++) if (lg[e] > lg[i0]) i0 = e;
        int i1 = (i0 == 0) ? 1 : 0;
        #pragma unroll
        for (int e=0;e<8;e++) if (e != i0 && lg[e] > lg[i1]) i1 = e;
        float e1 = expf(lg[i1]-lg[i0]);
        float inv = 1.f/(1.f+e1);
        float w0 = inv, w1 = e1*inv;
        int p0 = atomicAdd(&g_cnt[i0],1);
        g_elist[i0*NTOK+p0]=t; g_ew[i0*NTOK+p0]=w0;
        g_tslot[t*2]   = i0*NTOK + p0;
        int p1 = atomicAdd(&g_cnt[i1],1);
        g_elist[i1*NTOK+p1]=t; g_ew[i1*NTOK+p1]=w1;
        g_tslot[t*2+1] = i1*NTOK + p1;
    }
}

// ---------------- zero counters ----------------
__global__ void zcnt_kernel(){ if (threadIdx.x < Ev) g_cnt[threadIdx.x] = 0; }

// ---------------- final: gather 2 expert slots; mom_new; h2 = LN(h1 - mom_new) ----------------
__global__ void final_kernel(const float* __restrict__ mom, const float* __restrict__ g,
                             const float* __restrict__ bet, float* __restrict__ out, int write_mom)
{
    int row = blockIdx.x, tid = threadIdx.x;
    int s0 = g_tslot[row*2], s1 = g_tslot[row*2+1];
    float4 y0 = ((const float4*)(g_y + (size_t)s0*Hv))[tid];
    float4 y1 = ((const float4*)(g_y + (size_t)s1*Hv))[tid];
    float4 mm = ((const float4*)(mom + (size_t)row*Hv))[tid];
    float4 mn;
    mn.x = 0.7f*mm.x + y0.x + y1.x; mn.y = 0.7f*mm.y + y0.y + y1.y;
    mn.z = 0.7f*mm.z + y0.z + y1.z; mn.w = 0.7f*mm.w + y0.w + y1.w;
    float4 h1v = ((const float4*)(g_h1 + (size_t)row*Hv))[tid];
    float4 x;
    x.x = h1v.x - mn.x; x.y = h1v.y - mn.y; x.z = h1v.z - mn.z; x.w = h1v.w - mn.w;
    __shared__ float rs[256], rq[256];
    rs[tid] = x.x+x.y+x.z+x.w;
    rq[tid] = x.x*x.x + x.y*x.y + x.z*x.z + x.w*x.w;
    __syncthreads();
    for (int t=128;t>0;t>>=1){ if(tid<t){rs[tid]+=rs[tid+t]; rq[tid]+=rq[tid+t];} __syncthreads(); }
    float mean = rs[0] * (1.f/(float)Hv);
    float var  = rq[0] * (1.f/(float)Hv) - mean*mean;
    float inv = rsqrtf(var + 1e-5f);
    float4 gg = ((const float4*)g)[tid];
    float4 bb = ((const float4*)bet)[tid];
    float4 o;
    o.x = (x.x-mean)*inv*gg.x + bb.x;
    o.y = (x.y-mean)*inv*gg.y + bb.y;
    o.z = (x.z-mean)*inv*gg.z + bb.z;
    o.w = (x.w-mean)*inv*gg.w + bb.w;
    ((float4*)(out + (size_t)row*Hv))[tid] = o;
    if (write_mom)
        ((float4*)(out + (size_t)NTOK*Hv + (size_t)row*Hv))[tid] = mn;
}

extern "C" void kernel_launch(void* const* d_in, const int* in_sizes, int n_in,
                              void* d_out, int out_size)
{
    const float* h       = (const float*)d_in[0];
    const float* h_cache = (const float*)d_in[1];
    const float* pos     = (const float*)d_in[2];
    const float* mom     = (const float*)d_in[3];
    const float* Wq      = (const float*)d_in[4];
    const float* Wk      = (const float*)d_in[5];
    const float* Wv      = (const float*)d_in[6];
    const float* Wo      = (const float*)d_in[7];
    const float* gw      = (const float*)d_in[8];
    const float* gb      = (const float*)d_in[9];
    const float* w1      = (const float*)d_in[10];
    const float* b1      = (const float*)d_in[11];
    const float* w2      = (const float*)d_in[12];
    const float* b2      = (const float*)d_in[13];
    const float* ln1g    = (const float*)d_in[14];
    const float* ln1b    = (const float*)d_in[15];
    const float* ln2g    = (const float*)d_in[16];
    const float* ln2b    = (const float*)d_in[17];
    float* out = (float*)d_out;

    float *p_sskew, *p_y, *p_ew, *p_proj, *p_opart, *p_ml;
    __half *p_h16, *p_hall16, *p_q16, *p_k16, *p_v16, *p_pos16;
    __half *p_wq, *p_wk, *p_wv, *p_wo, *p_w1h, *p_w2h, *p_attn16, *p_h1h, *p_act16;
    int *p_cnt, *p_elist;
    cudaGetSymbolAddress((void**)&p_sskew, g_sskew);
    cudaGetSymbolAddress((void**)&p_y, g_y);
    cudaGetSymbolAddress((void**)&p_ew, g_ew);
    cudaGetSymbolAddress((void**)&p_cnt, g_cnt);
    cudaGetSymbolAddress((void**)&p_elist, g_elist);
    cudaGetSymbolAddress((void**)&p_opart, g_opart);
    cudaGetSymbolAddress((void**)&p_ml, g_ml);
    cudaGetSymbolAddress((void**)&p_h16, g_h16);
    cudaGetSymbolAddress((void**)&p_hall16, g_hall16);
    cudaGetSymbolAddress((void**)&p_q16, g_q16);
    cudaGetSymbolAddress((void**)&p_k16, g_k16);
    cudaGetSymbolAddress((void**)&p_v16, g_v16);
    cudaGetSymbolAddress((void**)&p_pos16, g_pos16);
    cudaGetSymbolAddress((void**)&p_wq, g_wq16);
    cudaGetSymbolAddress((void**)&p_wk, g_wk16);
    cudaGetSymbolAddress((void**)&p_wv, g_wv16);
    cudaGetSymbolAddress((void**)&p_wo, g_wo16);
    cudaGetSymbolAddress((void**)&p_w1h, g_w1h);
    cudaGetSymbolAddress((void**)&p_w2h, g_w2h);
    cudaGetSymbolAddress((void**)&p_attn16, g_attn16);
    cudaGetSymbolAddress((void**)&p_h1h, g_h1h);
    cudaGetSymbolAddress((void**)&p_act16, g_act16);
    cudaGetSymbolAddress((void**)&p_proj, g_proj);

    cudaFuncSetAttribute(hgemm<0>, cudaFuncAttributeMaxDynamicSharedMemorySize, SMEMSZ);
    cudaFuncSetAttribute(hgemm<1>, cudaFuncAttributeMaxDynamicSharedMemorySize, SMEMSZ);
    cudaFuncSetAttribute(hgemm<2>, cudaFuncAttributeMaxDynamicSharedMemorySize, SMEMSZ);
    cudaFuncSetAttribute(hgemm<3>, cudaFuncAttributeMaxDynamicSharedMemorySize, SMEMSZ);
    cudaFuncSetAttribute(hgemm<4>, cudaFuncAttributeMaxDynamicSharedMemorySize, SMEMSZ);
    cudaFuncSetAttribute(flash_kernel, cudaFuncAttributeMaxDynamicSharedMemorySize, FSMEM);

    static cudaStream_t s2 = nullptr;
    static cudaEvent_t evF = nullptr, evH = nullptr, evPos = nullptr, evWo = nullptr, evW12 = nullptr;
    if (!s2) {
        cudaStreamCreateWithFlags(&s2, cudaStreamNonBlocking);
        cudaEventCreateWithFlags(&evF,   cudaEventDisableTiming);
        cudaEventCreateWithFlags(&evH,   cudaEventDisableTiming);
        cudaEventCreateWithFlags(&evPos, cudaEventDisableTiming);
        cudaEventCreateWithFlags(&evWo,  cudaEventDisableTiming);
        cudaEventCreateWithFlags(&evW12, cudaEventDisableTiming);
    }

    int write_mom = (out_size >= 2*NTOK*Hv) ? 1 : 0;

    // ---- fork ----
    cudaEventRecord(evF, 0);
    cudaStreamWaitEvent(s2, evF, 0);

    // main stream: concat + h16 -> K/V projections
    concat_kernel<<<8192, 256>>>(h_cache, h);
    cvt_kernel<<<2048, 256>>>(h, p_h16, (size_t)NTOK*Hv);
    cudaEventRecord(evH, 0);
    zcnt_kernel<<<1, 32>>>();
    cvt_kernel<<<512, 256>>>(Wk, p_wk, (size_t)Hv*Hv);
    hgemm<4><<<dim3(8,64), 256, SMEMSZ>>>(p_hall16, p_wk, nullptr, p_k16, Bv*LMv, Hv, Hv, Hv, nullptr, nullptr, nullptr, nullptr);
    cvt_kernel<<<512, 256>>>(Wv, p_wv, (size_t)Hv*Hv);
    hgemm<4><<<dim3(8,64), 256, SMEMSZ>>>(p_hall16, p_wv, nullptr, p_v16, Bv*LMv, Hv, Hv, Hv, nullptr, nullptr, nullptr, nullptr);

    // side stream: Wq/pos cvt -> Q proj -> pos GEMM -> Wo/w1/w2 cvt
    cvt_kernel<<<512, 256, 0, s2>>>(Wq, p_wq, (size_t)Hv*Hv);
    cvt_kernel<<<64,  256, 0, s2>>>(pos, p_pos16, (size_t)Dv*Lv);
    cudaStreamWaitEvent(s2, evH, 0);
    hgemm<4><<<dim3(8,32), 256, SMEMSZ, s2>>>(p_h16, p_wq, nullptr, p_q16, NTOK, Hv, Hv, Hv, nullptr, nullptr, nullptr, nullptr);
    hgemm<3><<<dim3(8,8,32), 256, SMEMSZ, s2>>>(p_q16, p_pos16, p_sskew, nullptr, Mv, Lv, Dv, Hv, nullptr, nullptr, nullptr, nullptr);
    cudaEventRecord(evPos, s2);
    cvt_kernel<<<512, 256, 0, s2>>>(Wo, p_wo, (size_t)Hv*Hv);
    cudaEventRecord(evWo, s2);
    cvt_kernel<<<16384, 256, 0, s2>>>(w1, p_w1h, (size_t)Ev*Hv*Fv);
    cvt_kernel<<<16384, 256, 0, s2>>>(w2, p_w2h, (size_t)Ev*Fv*Hv);
    cudaEventRecord(evW12, s2);

    // main stream: split-KV flash + combine
    cudaStreamWaitEvent(0, evPos, 0);
    flash_kernel<<<dim3(8,32,NSPL), 256, FSMEM>>>(p_q16, p_k16, p_v16, p_sskew, p_opart, p_ml);
    combine_kernel<<<BHv*Mv, 128>>>(p_opart, p_ml, p_attn16);
    // Wo projection + LN1 + gate
    cudaStreamWaitEvent(0, evWo, 0);
    hgemm<0><<<dim3(8,32), 256, SMEMSZ>>>(p_attn16, p_wo, p_proj, nullptr, NTOK, Hv, Hv, Hv, nullptr, nullptr, nullptr, nullptr);
    ln1_kernel<<<NTOK, 256>>>(h, ln1g, ln1b);
    gate_kernel<<<NTOK, 256>>>(gw, gb);
    // MoE (expert-parallel; atomic-free combine)
    cudaStreamWaitEvent(0, evW12, 0);
    hgemm<1><<<dim3(32,32,Ev), 256, SMEMSZ>>>(p_h1h, p_w1h, nullptr, p_act16, NTOK, Fv, Hv, Hv,
                                              p_elist, p_cnt, b1, nullptr);
    hgemm<2><<<dim3(8,32,Ev), 256, SMEMSZ>>>(p_act16, p_w2h, p_y, nullptr, NTOK, Hv, Fv, Fv,
                                             nullptr, p_cnt, b2, p_ew);
    // gather + momentum + LN2 + outputs
    final_kernel<<<NTOK, 256>>>(mom, ln2g, ln2b, out, write_mom);
}